// round 16
// baseline (speedup 1.0000x reference)
#include <cuda_runtime.h>
#include <cuda_fp16.h>
#include <cuda_pipeline.h>
#include <mma.h>
#include <cstdint>

using namespace nvcuda;

#define N_NODES 16384
#define N_EDGES 131072
#define ED      32
#define NGRAPH  128
#define MAXF    1024
#define NEG_SLOPE 0.2f

// ---------------- scratch (static device memory; no allocs) ----------------
__device__ float g_hA[(size_t)N_NODES * 256];      // layer-3 output (fp32, for pool)
__device__ float g_xl[(size_t)N_NODES * MAXF];
__device__ float g_xr[(size_t)N_NODES * MAXF];
__device__ __half g_Ah[(size_t)N_NODES * MAXF];    // split activations hi
__device__ __half g_Al[(size_t)N_NODES * MAXF];    // lo
#define WOFF_L1 0
#define WOFF_R1 131072
#define WOFF_L2 262144
#define WOFF_R2 786432
#define WOFF_L3 1310720
#define WOFF_R3 1572864
#define WTOTAL  1835008
__device__ __half g_Wh[WTOTAL];
__device__ __half g_Wlo[WTOTAL];
#define WEOFF_1 0
#define WEOFF_2 16384
#define WEOFF_3 49152
#define WETOTAL 57344
__device__ __half g_weh[WETOTAL];
__device__ __half g_wel[WETOTAL];
__device__ __half g_eah[(size_t)N_EDGES * ED];
__device__ __half g_eal[(size_t)N_EDGES * ED];
__device__ __half g_lah[N_NODES * ED];
__device__ __half g_lal[N_NODES * ED];
__device__ int   g_deg[N_NODES];
__device__ int   g_off[N_NODES + 1];
__device__ int   g_cur[N_NODES];
__device__ int   g_ssrc[N_EDGES];
__device__ int   g_sdst[N_EDGES];
__device__ int   g_seid[N_EDGES];
__device__ float g_elog[N_EDGES];     // logits, then normalized alphas (in-place)
__device__ float g_eself[N_NODES];    // self logit, then alpha_self
__device__ float g_pool[NGRAPH * 256];
__device__ float g_z[NGRAPH * 64];

// ---------------- utility kernels ----------------
__global__ void zero_deg_cur() {
    int i = blockIdx.x * blockDim.x + threadIdx.x;
    if (i < N_NODES) { g_deg[i] = 0; g_cur[i] = 0; }
}

__global__ void count_deg(const int* __restrict__ dst) {
    int i = blockIdx.x * blockDim.x + threadIdx.x;
    if (i < N_EDGES) atomicAdd(&g_deg[dst[i]], 1);
}

__global__ void scan_deg() {
    int tid = threadIdx.x, lane = tid & 31, warp = tid >> 5;
    int base = tid * 16;
    int loc[16];
    int s = 0;
#pragma unroll
    for (int k = 0; k < 16; k++) { loc[k] = s; s += g_deg[base + k]; }
    int mysum = s;
#pragma unroll
    for (int o = 1; o < 32; o <<= 1) {
        int v = __shfl_up_sync(0xffffffffu, s, o);
        if (lane >= o) s += v;
    }
    __shared__ int wsum[32];
    if (lane == 31) wsum[warp] = s;
    __syncthreads();
    if (warp == 0) {
        int v = wsum[lane];
#pragma unroll
        for (int o = 1; o < 32; o <<= 1) {
            int u = __shfl_up_sync(0xffffffffu, v, o);
            if (lane >= o) v += u;
        }
        wsum[lane] = v;
    }
    __syncthreads();
    int excl = s - mysum + (warp ? wsum[warp - 1] : 0);
#pragma unroll
    for (int k = 0; k < 16; k++) g_off[base + k] = excl + loc[k];
    if (tid == 1023) g_off[N_NODES] = excl + mysum;
}

__global__ void scatter_edges(const int* __restrict__ src, const int* __restrict__ dst) {
    int i = blockIdx.x * blockDim.x + threadIdx.x;
    if (i >= N_EDGES) return;
    int d = dst[i];
    int p = g_off[d] + atomicAdd(&g_cur[d], 1);
    g_ssrc[p] = src[i];
    g_sdst[p] = d;
    g_seid[p] = i;
}

__global__ void ea_presplit(const float* __restrict__ ea) {
    int idx = blockIdx.x * blockDim.x + threadIdx.x;
    if (idx >= N_EDGES * 8) return;
    int p = idx >> 3, q = idx & 7;
    int row = g_seid[p];
    float4 v = *reinterpret_cast<const float4*>(&ea[(size_t)row * ED + q * 4]);
    float vv[4] = {v.x, v.y, v.z, v.w};
    __half h[4], l[4];
#pragma unroll
    for (int i = 0; i < 4; i++) {
        h[i] = __float2half_rn(vv[i]);
        l[i] = __float2half_rn(vv[i] - __half2float(h[i]));
    }
    *reinterpret_cast<uint2*>(&g_eah[(size_t)p * ED + q * 4]) = *reinterpret_cast<uint2*>(h);
    *reinterpret_cast<uint2*>(&g_eal[(size_t)p * ED + q * 4]) = *reinterpret_cast<uint2*>(l);
}

__global__ void loop_attr_csr(const float* __restrict__ ea) {
    int w = (blockIdx.x * blockDim.x + threadIdx.x) >> 5;
    int lane = threadIdx.x & 31;
    if (w >= N_NODES) return;
    int off = g_off[w], deg = g_off[w + 1] - off;
    float a = 0.0f;
    for (int j = 0; j < deg; j++)
        a += ea[(size_t)g_seid[off + j] * ED + lane];
    a /= fmaxf((float)deg, 1.0f);
    __half h = __float2half_rn(a);
    g_lah[w * ED + lane] = h;
    g_lal[w * ED + lane] = __float2half_rn(a - __half2float(h));
}

// ---------------- fp32 -> (hi,lo) fp16 split ----------------
__global__ void split_kernel(const float* __restrict__ in,
                             __half* __restrict__ hi, __half* __restrict__ lo, int n) {
    int base = (blockIdx.x * blockDim.x + threadIdx.x) * 4;
    if (base >= n) return;
    float4 v = *reinterpret_cast<const float4*>(in + base);
    float vv[4] = {v.x, v.y, v.z, v.w};
    __half h[4], l[4];
#pragma unroll
    for (int i = 0; i < 4; i++) {
        h[i] = __float2half_rn(vv[i]);
        l[i] = __float2half_rn(vv[i] - __half2float(h[i]));
    }
    *reinterpret_cast<uint2*>(hi + base) = *reinterpret_cast<uint2*>(h);
    *reinterpret_cast<uint2*>(lo + base) = *reinterpret_cast<uint2*>(l);
}

// ------- pre-split fp16x2 GEMM, 4 warps x 64x64 tiles, 2-stage cp.async -------
#define G4_LDA 40
#define G4_LDB 136
#define G4_AOFF_L 5120
#define G4_BOFF   10240
#define G4_BOFF_L 14592
#define G4_STAGE  18944
#define G4_SMEM   (2 * G4_STAGE * 2)      // 75776 B -> 2 CTAs/SM

__global__ __launch_bounds__(128, 2) void gemm4w(
    const __half* __restrict__ Ah, const __half* __restrict__ Al,
    const __half* __restrict__ B0h, const __half* __restrict__ B0l,
    const __half* __restrict__ B1h, const __half* __restrict__ B1l,
    const float* __restrict__ bias0, const float* __restrict__ bias1,
    float* __restrict__ C0, float* __restrict__ C1,
    int M, int Nw, int K) {
    extern __shared__ char gsm[];
    __half* sm = reinterpret_cast<__half*>(gsm);

    int tid = threadIdx.x;
    int warp = tid >> 5, lane = tid & 31;
    int wr = warp >> 1, wc = warp & 1;
    int nbx = Nw >> 7;
    int bx = blockIdx.x;
    const __half *Bh, *Bl;
    const float* bias;
    float* C;
    int col0;
    if (bx < nbx) { Bh = B0h; Bl = B0l; bias = bias0; C = C0; col0 = bx << 7; }
    else          { Bh = B1h; Bl = B1l; bias = bias1; C = C1; col0 = (bx - nbx) << 7; }
    int row0 = blockIdx.y << 7;

    wmma::fragment<wmma::accumulator, 16, 16, 16, float> cf[4][4];
#pragma unroll
    for (int r = 0; r < 4; r++)
#pragma unroll
        for (int c = 0; c < 4; c++) wmma::fill_fragment(cf[r][c], 0.0f);

    auto copy_stage = [&](int t) {
        int k0 = t * 32;
        __half* sb = sm + (t & 1) * G4_STAGE;
#pragma unroll
        for (int q = 0; q < 4; q++) {
            int idx = tid + q * 128;
            int r = idx >> 2, c = idx & 3;
            __pipeline_memcpy_async(&sb[r * G4_LDA + c * 8],
                                    &Ah[(size_t)(row0 + r) * K + k0 + c * 8], 16);
            __pipeline_memcpy_async(&sb[G4_AOFF_L + r * G4_LDA + c * 8],
                                    &Al[(size_t)(row0 + r) * K + k0 + c * 8], 16);
            int rb = idx >> 4, cb = idx & 15;
            __pipeline_memcpy_async(&sb[G4_BOFF + rb * G4_LDB + cb * 8],
                                    &Bh[(size_t)(k0 + rb) * Nw + col0 + cb * 8], 16);
            __pipeline_memcpy_async(&sb[G4_BOFF_L + rb * G4_LDB + cb * 8],
                                    &Bl[(size_t)(k0 + rb) * Nw + col0 + cb * 8], 16);
        }
    };
    auto compute = [&](int slot) {
        const __half* sb = sm + slot * G4_STAGE;
#pragma unroll
        for (int ks = 0; ks < 2; ks++) {
            wmma::fragment<wmma::matrix_a, 16, 16, 16, __half, wmma::row_major> ah[4], al[4];
            wmma::fragment<wmma::matrix_b, 16, 16, 16, __half, wmma::row_major> bh[4], bl[4];
#pragma unroll
            for (int r = 0; r < 4; r++) {
                int aoff = (wr * 64 + r * 16) * G4_LDA + ks * 16;
                wmma::load_matrix_sync(ah[r], &sb[aoff], G4_LDA);
                wmma::load_matrix_sync(al[r], &sb[G4_AOFF_L + aoff], G4_LDA);
            }
#pragma unroll
            for (int c = 0; c < 4; c++) {
                int boff = (ks * 16) * G4_LDB + wc * 64 + c * 16;
                wmma::load_matrix_sync(bh[c], &sb[G4_BOFF + boff], G4_LDB);
                wmma::load_matrix_sync(bl[c], &sb[G4_BOFF_L + boff], G4_LDB);
            }
#pragma unroll
            for (int r = 0; r < 4; r++)
#pragma unroll
                for (int c = 0; c < 4; c++) {
                    wmma::mma_sync(cf[r][c], ah[r], bl[c], cf[r][c]);
                    wmma::mma_sync(cf[r][c], al[r], bh[c], cf[r][c]);
                    wmma::mma_sync(cf[r][c], ah[r], bh[c], cf[r][c]);
                }
        }
    };

    int nk = K >> 5;
    copy_stage(0);
    __pipeline_commit();
    for (int t = 0; t < nk; t++) {
        __pipeline_wait_prior(0);
        __syncthreads();
        if (t + 1 < nk) {
            copy_stage(t + 1);
            __pipeline_commit();
        }
        compute(t & 1);
    }
    __syncthreads();

    float* Ep = reinterpret_cast<float*>(gsm) + warp * 16 * 20;
    int erow = lane >> 1;
    int ecol = (lane & 1) * 8;
#pragma unroll
    for (int r = 0; r < 4; r++) {
#pragma unroll
        for (int c = 0; c < 4; c++) {
            wmma::store_matrix_sync(Ep, cf[r][c], 20, wmma::mem_row_major);
            __syncwarp();
            int rr = row0 + wr * 64 + r * 16 + erow;
            int cc = col0 + wc * 64 + c * 16 + ecol;
            float4 v0 = *reinterpret_cast<float4*>(&Ep[erow * 20 + ecol]);
            float4 v1 = *reinterpret_cast<float4*>(&Ep[erow * 20 + ecol + 4]);
            float4 b0 = *reinterpret_cast<const float4*>(&bias[cc]);
            float4 b1 = *reinterpret_cast<const float4*>(&bias[cc + 4]);
            v0.x += b0.x; v0.y += b0.y; v0.z += b0.z; v0.w += b0.w;
            v1.x += b1.x; v1.y += b1.y; v1.z += b1.z; v1.w += b1.w;
            *reinterpret_cast<float4*>(&C[(size_t)rr * Nw + cc])     = v0;
            *reinterpret_cast<float4*>(&C[(size_t)rr * Nw + cc + 4]) = v1;
            __syncwarp();
        }
    }
}

// ------- fused attention logits (edges + self-loops in ONE launch) -------
// dst-sorted tiles: xr[dst] rows repeat ~8x consecutively -> warp-uniform
// register caching of the vr gather eliminates ~7/8 of xr loads.
#define FL_LDE 40
#define FL_LDW 136
#define FL_LDZ 132
#define FL_SMEM (2*128*FL_LDE*2 + 2*32*FL_LDW*2 + 128*FL_LDZ*4 + 2*128*4)
#define FL_EDGE_BLOCKS (N_EDGES / 128)

__global__ __launch_bounds__(256) void fused_logit(
    const __half* __restrict__ weh, const __half* __restrict__ wel,
    const float* __restrict__ att,
    const float* __restrict__ xl, const float* __restrict__ xr,
    float* __restrict__ elog, float* __restrict__ eself, int F) {
    extern __shared__ char sm_raw[];
    __half* ea_h = reinterpret_cast<__half*>(sm_raw);
    __half* ea_l = ea_h + 128 * FL_LDE;
    __half* w_h  = ea_l + 128 * FL_LDE;
    __half* w_l  = w_h + 32 * FL_LDW;
    float*  sz   = reinterpret_cast<float*>(w_l + 32 * FL_LDW);
    int* s_src = reinterpret_cast<int*>(sz + 128 * FL_LDZ);
    int* s_dst = s_src + 128;

    int tid = threadIdx.x, warp = tid >> 5, lane = tid & 31;
    int wr = warp >> 2, wc = warp & 3;
    int mode = (blockIdx.x >= FL_EDGE_BLOCKS) ? 1 : 0;
    int tile0 = (mode == 0) ? blockIdx.x * 128 : (blockIdx.x - FL_EDGE_BLOCKS) * 128;
    const __half* eah = (mode == 0) ? g_eah : g_lah;
    const __half* eal = (mode == 0) ? g_eal : g_lal;
    float* out_log = (mode == 0) ? elog : eself;

    if (tid < 128) {
        if (mode == 0) { s_src[tid] = g_ssrc[tile0 + tid]; s_dst[tid] = g_sdst[tile0 + tid]; }
        else           { s_src[tid] = tile0 + tid;         s_dst[tid] = tile0 + tid; }
    }
    {
        size_t base = (size_t)tile0 * ED;
#pragma unroll
        for (int q = 0; q < 2; q++) {
            int ch = tid + q * 256;
            int r = ch >> 2, c8 = ch & 3;
            *reinterpret_cast<uint4*>(&ea_h[r * FL_LDE + c8 * 8]) =
                __ldg(reinterpret_cast<const uint4*>(&eah[base + ch * 8]));
            *reinterpret_cast<uint4*>(&ea_l[r * FL_LDE + c8 * 8]) =
                __ldg(reinterpret_cast<const uint4*>(&eal[base + ch * 8]));
        }
    }
    __syncthreads();

    float acc[16];
#pragma unroll
    for (int e = 0; e < 16; e++) acc[e] = 0.0f;
    int we0 = warp * 16;

    for (int f0 = 0; f0 < F; f0 += 128) {
#pragma unroll
        for (int q = 0; q < 2; q++) {
            int ch = tid + q * 256;
            int r = ch >> 4, c8 = ch & 15;
            *reinterpret_cast<uint4*>(&w_h[r * FL_LDW + c8 * 8]) =
                __ldg(reinterpret_cast<const uint4*>(&weh[(size_t)r * F + f0 + c8 * 8]));
            *reinterpret_cast<uint4*>(&w_l[r * FL_LDW + c8 * 8]) =
                __ldg(reinterpret_cast<const uint4*>(&wel[(size_t)r * F + f0 + c8 * 8]));
        }
        __syncthreads();

        wmma::fragment<wmma::accumulator, 16, 16, 16, float> cf[4][2];
#pragma unroll
        for (int r = 0; r < 4; r++)
#pragma unroll
            for (int c = 0; c < 2; c++) wmma::fill_fragment(cf[r][c], 0.0f);
#pragma unroll
        for (int ks = 0; ks < 2; ks++) {
            wmma::fragment<wmma::matrix_a, 16, 16, 16, __half, wmma::row_major> ah[4], al[4];
            wmma::fragment<wmma::matrix_b, 16, 16, 16, __half, wmma::row_major> bh[2], bl[2];
#pragma unroll
            for (int r = 0; r < 4; r++) {
                int aoff = (wr * 64 + r * 16) * FL_LDE + ks * 16;
                wmma::load_matrix_sync(ah[r], &ea_h[aoff], FL_LDE);
                wmma::load_matrix_sync(al[r], &ea_l[aoff], FL_LDE);
            }
#pragma unroll
            for (int c = 0; c < 2; c++) {
                int boff = (ks * 16) * FL_LDW + wc * 32 + c * 16;
                wmma::load_matrix_sync(bh[c], &w_h[boff], FL_LDW);
                wmma::load_matrix_sync(bl[c], &w_l[boff], FL_LDW);
            }
#pragma unroll
            for (int r = 0; r < 4; r++)
#pragma unroll
                for (int c = 0; c < 2; c++) {
                    wmma::mma_sync(cf[r][c], ah[r], bl[c], cf[r][c]);
                    wmma::mma_sync(cf[r][c], al[r], bh[c], cf[r][c]);
                    wmma::mma_sync(cf[r][c], ah[r], bh[c], cf[r][c]);
                }
        }
#pragma unroll
        for (int r = 0; r < 4; r++)
#pragma unroll
            for (int c = 0; c < 2; c++)
                wmma::store_matrix_sync(&sz[(wr * 64 + r * 16) * FL_LDZ + wc * 32 + c * 16],
                                        cf[r][c], FL_LDZ, wmma::mem_row_major);
        __syncthreads();

        float4 av = *reinterpret_cast<const float4*>(&att[f0 + lane * 4]);
        float4 vr = make_float4(0.f, 0.f, 0.f, 0.f);
        int prev_dst = -1;   // warp-uniform cache of the xr[dst] row chunk
#pragma unroll
        for (int e = 0; e < 16; e++) {
            int idx = we0 + e;
            float4 vl = __ldg(reinterpret_cast<const float4*>(xl + (size_t)s_src[idx] * F + f0 + lane * 4));
            int d = s_dst[idx];
            if (d != prev_dst) {   // uniform branch: s_dst[idx] identical across lanes
                vr = __ldg(reinterpret_cast<const float4*>(xr + (size_t)d * F + f0 + lane * 4));
                prev_dst = d;
            }
            float4 vz = *reinterpret_cast<const float4*>(&sz[idx * FL_LDZ + lane * 4]);
            float v0 = vl.x + vr.x + vz.x; v0 = (v0 > 0.0f) ? v0 : NEG_SLOPE * v0;
            float v1 = vl.y + vr.y + vz.y; v1 = (v1 > 0.0f) ? v1 : NEG_SLOPE * v1;
            float v2 = vl.z + vr.z + vz.z; v2 = (v2 > 0.0f) ? v2 : NEG_SLOPE * v2;
            float v3 = vl.w + vr.w + vz.w; v3 = (v3 > 0.0f) ? v3 : NEG_SLOPE * v3;
            acc[e] += v0 * av.x + v1 * av.y + v2 * av.z + v3 * av.w;
        }
        __syncthreads();
    }
#pragma unroll
    for (int e = 0; e < 16; e++) {
        float a = acc[e];
#pragma unroll
        for (int o = 16; o; o >>= 1) a += __shfl_xor_sync(0xffffffffu, a, o);
        if (lane == 0) out_log[tile0 + we0 + e] = a;
    }
}

// ------- per-node softmax stats: logits -> normalized alphas (in-place) -------
__global__ void softmax_stats() {
    int n = (blockIdx.x * blockDim.x + threadIdx.x) >> 5;
    int lane = threadIdx.x & 31;
    if (n >= N_NODES) return;
    int off = g_off[n], deg = g_off[n + 1] - off;
    float es = g_eself[n];
    float m = es;
    for (int j = lane; j < deg; j += 32) m = fmaxf(m, g_elog[off + j]);
#pragma unroll
    for (int o = 16; o; o >>= 1) m = fmaxf(m, __shfl_xor_sync(0xffffffffu, m, o));
    float s = 0.0f;
    for (int j = lane; j < deg; j += 32) s += __expf(g_elog[off + j] - m);
#pragma unroll
    for (int o = 16; o; o >>= 1) s += __shfl_xor_sync(0xffffffffu, s, o);
    float esx = __expf(es - m);
    float inv = 1.0f / (s + esx);
    for (int j = lane; j < deg; j += 32)
        g_elog[off + j] = __expf(g_elog[off + j] - m) * inv;
    if (lane == 0) g_eself[n] = esx * inv;
}

// ------- aggregate: weighted gather using precomputed alphas (+bias+relu) -------
template <int NR, bool SPLIT>
__global__ __launch_bounds__(256) void aggregate(const float* __restrict__ bc,
                                                 float* __restrict__ outf,
                                                 __half* __restrict__ outh,
                                                 __half* __restrict__ outl, int F) {
    int n = blockIdx.x;
    int tid = threadIdx.x;
    int off = g_off[n];
    int deg = g_off[n + 1] - off;
    __shared__ float s_alpha[256];
    __shared__ int s_src[256];

    int f0 = tid * NR;
    float acc[NR];
    const float* xln = &g_xl[(size_t)n * F];
    float aself = g_eself[n];
#pragma unroll
    for (int i = 0; i < NR; i++) acc[i] = aself * xln[f0 + i];

    for (int c0 = 0; c0 < deg; c0 += 256) {
        int cnt = min(256, deg - c0);
        if (tid < cnt) {
            s_alpha[tid] = g_elog[off + c0 + tid];
            s_src[tid] = g_ssrc[off + c0 + tid];
        }
        __syncthreads();
        for (int j = 0; j < cnt; j++) {
            const float* xs = &g_xl[(size_t)s_src[j] * F];
            float a = s_alpha[j];
            if (NR == 4) {
                float4 v = __ldg(reinterpret_cast<const float4*>(xs + f0));
                acc[0] += a * v.x; acc[1] += a * v.y;
                acc[2] += a * v.z; acc[3] += a * v.w;
            } else if (NR == 2) {
                float2 v = __ldg(reinterpret_cast<const float2*>(xs + f0));
                acc[0] += a * v.x; acc[1] += a * v.y;
            } else {
                acc[0] += a * __ldg(xs + f0);
            }
        }
        __syncthreads();
    }
    if (SPLIT) {
        __half h[NR], l[NR];
#pragma unroll
        for (int i = 0; i < NR; i++) {
            float v = fmaxf(acc[i] + bc[f0 + i], 0.0f);
            h[i] = __float2half_rn(v);
            l[i] = __float2half_rn(v - __half2float(h[i]));
        }
        size_t o = (size_t)n * F + f0;
        if (NR == 4) {
            *reinterpret_cast<uint2*>(&outh[o]) = *reinterpret_cast<uint2*>(h);
            *reinterpret_cast<uint2*>(&outl[o]) = *reinterpret_cast<uint2*>(l);
        } else {
            *reinterpret_cast<uint32_t*>(&outh[o]) = *reinterpret_cast<uint32_t*>(h);
            *reinterpret_cast<uint32_t*>(&outl[o]) = *reinterpret_cast<uint32_t*>(l);
        }
    } else {
#pragma unroll
        for (int i = 0; i < NR; i++)
            outf[(size_t)n * F + f0 + i] = fmaxf(acc[i] + bc[f0 + i], 0.0f);
    }
}

// ---------------- pooling ----------------
__global__ __launch_bounds__(256) void pool_graph(const float* __restrict__ h,
                                                  const int* __restrict__ batch) {
    int g = blockIdx.x;
    int tid = threadIdx.x;
    __shared__ int s_lo, s_hi;
    if (tid == 0) {
        int lo = 0, hi = N_NODES;
        while (lo < hi) { int mid = (lo + hi) >> 1; if (batch[mid] < g) lo = mid + 1; else hi = mid; }
        s_lo = lo;
        lo = 0; hi = N_NODES;
        while (lo < hi) { int mid = (lo + hi) >> 1; if (batch[mid] < g + 1) lo = mid + 1; else hi = mid; }
        s_hi = lo;
    }
    __syncthreads();
    int lo = s_lo, hi = s_hi;
    float acc = 0.0f;
    for (int n = lo; n < hi; n++) acc += h[(size_t)n * 256 + tid];
    g_pool[g * 256 + tid] = acc / fmaxf((float)(hi - lo), 1.0f);
}

// ---------------- MLP head ----------------
__global__ void fc1_kernel(const float* __restrict__ fc1w, const float* __restrict__ fc1b) {
    int i = blockIdx.x * blockDim.x + threadIdx.x;
    if (i >= NGRAPH * 64) return;
    int g = i >> 6, o = i & 63;
    float s = 0.0f;
    for (int k = 0; k < 256; k++) s += g_pool[g * 256 + k] * fc1w[k * 64 + o];
    g_z[i] = s + fc1b[o];
}

__global__ __launch_bounds__(256) void head_kernel(
    const float* __restrict__ bng, const float* __restrict__ bnb,
    const float* __restrict__ fc2w, const float* __restrict__ fc2b,
    float* __restrict__ out) {
    __shared__ float z[NGRAPH * 64];
    __shared__ float mu[64], iv[64];
    int tid = threadIdx.x;
    for (int i = tid; i < NGRAPH * 64; i += 256) z[i] = g_z[i];
    __syncthreads();
    if (tid < 64) {
        float s = 0.0f, s2 = 0.0f;
        for (int g = 0; g < NGRAPH; g++) {
            float v = z[g * 64 + tid];
            s += v; s2 += v * v;
        }
        float mean = s / (float)NGRAPH;
        float var = s2 / (float)NGRAPH - mean * mean;
        mu[tid] = mean;
        iv[tid] = rsqrtf(var + 1e-5f);
    }
    __syncthreads();
    for (int i = tid; i < NGRAPH * 64; i += 256) {
        int o = i & 63;
        float v = (z[i] - mu[o]) * iv[o] * bng[o] + bnb[o];
        z[i] = fmaxf(v, 0.0f);
    }
    __syncthreads();
    if (tid < NGRAPH) {
        float s = 0.0f;
        for (int o = 0; o < 64; o++) s += z[tid * 64 + o] * fc2w[o];
        out[tid] = s + fc2b[0];
    }
}

extern "C" void kernel_launch(void* const* d_in, const int* in_sizes, int n_in,
                              void* d_out, int out_size) {
    const float* x         = (const float*)d_in[0];
    const int*   ei        = (const int*)d_in[1];
    const float* edge_attr = (const float*)d_in[2];
    const int*   batch     = (const int*)d_in[3];

    const float* Wl[3], *bl[3], *Wr[3], *br[3], *We[3], *att[3], *bc[3];
    for (int l = 0; l < 3; l++) {
        int b = 4 + l * 7;
        Wl[l]  = (const float*)d_in[b + 0];
        bl[l]  = (const float*)d_in[b + 1];
        Wr[l]  = (const float*)d_in[b + 2];
        br[l]  = (const float*)d_in[b + 3];
        We[l]  = (const float*)d_in[b + 4];
        att[l] = (const float*)d_in[b + 5];
        bc[l]  = (const float*)d_in[b + 6];
    }
    const float* fc1w = (const float*)d_in[25];
    const float* fc1b = (const float*)d_in[26];
    const float* bng  = (const float*)d_in[27];
    const float* bnb  = (const float*)d_in[28];
    const float* fc2w = (const float*)d_in[29];
    const float* fc2b = (const float*)d_in[30];
    float* out = (float*)d_out;

    const int* src = ei;
    const int* dst = ei + N_EDGES;

    static cudaStream_t s2 = nullptr;
    static cudaEvent_t ev_fork = nullptr, ev_join = nullptr;
    static bool attr_set = false;
    if (!attr_set) {
        cudaFuncSetAttribute(fused_logit, cudaFuncAttributeMaxDynamicSharedMemorySize, FL_SMEM);
        cudaFuncSetAttribute(gemm4w, cudaFuncAttributeMaxDynamicSharedMemorySize, G4_SMEM);
        cudaStreamCreateWithFlags(&s2, cudaStreamNonBlocking);
        cudaEventCreateWithFlags(&ev_fork, cudaEventDisableTiming);
        cudaEventCreateWithFlags(&ev_join, cudaEventDisableTiming);
        attr_set = true;
    }

    float *d_hA, *d_xl, *d_xr, *d_elog, *d_eself;
    __half *d_Ah, *d_Al, *d_Wh, *d_Wlo, *d_weh, *d_wel;
    cudaGetSymbolAddress((void**)&d_hA, g_hA);
    cudaGetSymbolAddress((void**)&d_xl, g_xl);
    cudaGetSymbolAddress((void**)&d_xr, g_xr);
    cudaGetSymbolAddress((void**)&d_elog, g_elog);
    cudaGetSymbolAddress((void**)&d_eself, g_eself);
    cudaGetSymbolAddress((void**)&d_Ah, g_Ah);
    cudaGetSymbolAddress((void**)&d_Al, g_Al);
    cudaGetSymbolAddress((void**)&d_Wh, g_Wh);
    cudaGetSymbolAddress((void**)&d_Wlo, g_Wlo);
    cudaGetSymbolAddress((void**)&d_weh, g_weh);
    cudaGetSymbolAddress((void**)&d_wel, g_wel);

    const int woff[6]  = {WOFF_L1, WOFF_R1, WOFF_L2, WOFF_R2, WOFF_L3, WOFF_R3};
    const int wsz[3]   = {256 * 512, 512 * 1024, 1024 * 256};
    const int weoff[3] = {WEOFF_1, WEOFF_2, WEOFF_3};
    const int Fout[3]  = {512, 1024, 256};

    // ---- fork: preprocessing + remaining splits on side stream s2 ----
    cudaEventRecord(ev_fork, 0);
    cudaStreamWaitEvent(s2, ev_fork, 0);

    zero_deg_cur<<<(N_NODES + 255) / 256, 256, 0, s2>>>();
    count_deg<<<(N_EDGES + 255) / 256, 256, 0, s2>>>(dst);
    scan_deg<<<1, 1024, 0, s2>>>();
    scatter_edges<<<(N_EDGES + 255) / 256, 256, 0, s2>>>(src, dst);
    ea_presplit<<<(N_EDGES * 8 + 255) / 256, 256, 0, s2>>>(edge_attr);
    loop_attr_csr<<<(N_NODES * 32 + 255) / 256, 256, 0, s2>>>(edge_attr);
    split_kernel<<<(wsz[1] / 4 + 255) / 256, 256, 0, s2>>>(Wl[1], d_Wh + woff[2], d_Wlo + woff[2], wsz[1]);
    split_kernel<<<(wsz[1] / 4 + 255) / 256, 256, 0, s2>>>(Wr[1], d_Wh + woff[3], d_Wlo + woff[3], wsz[1]);
    split_kernel<<<(wsz[2] / 4 + 255) / 256, 256, 0, s2>>>(Wl[2], d_Wh + woff[4], d_Wlo + woff[4], wsz[2]);
    split_kernel<<<(wsz[2] / 4 + 255) / 256, 256, 0, s2>>>(Wr[2], d_Wh + woff[5], d_Wlo + woff[5], wsz[2]);
    for (int l = 0; l < 3; l++) {
        int n = ED * Fout[l];
        split_kernel<<<(n / 4 + 255) / 256, 256, 0, s2>>>(We[l], d_weh + weoff[l], d_wel + weoff[l], n);
    }
    cudaEventRecord(ev_join, s2);

    // main stream: x split + layer-1 weight splits + layer-1 GEMM (overlaps s2)
    split_kernel<<<(N_NODES * 256 / 4) / 256, 256>>>(x, d_Ah, d_Al, N_NODES * 256);
    split_kernel<<<(wsz[0] / 4 + 255) / 256, 256>>>(Wl[0], d_Wh + woff[0], d_Wlo + woff[0], wsz[0]);
    split_kernel<<<(wsz[0] / 4 + 255) / 256, 256>>>(Wr[0], d_Wh + woff[1], d_Wlo + woff[1], wsz[0]);
    {
        dim3 g(2 * 512 / 128, N_NODES / 128);
        gemm4w<<<g, 128, G4_SMEM>>>(d_Ah, d_Al, d_Wh + woff[0], d_Wlo + woff[0],
                                    d_Wh + woff[1], d_Wlo + woff[1],
                                    bl[0], br[0], d_xl, d_xr, N_NODES, 512, 256);
    }
    cudaStreamWaitEvent(0, ev_join, 0);

    // layer 1
    fused_logit<<<FL_EDGE_BLOCKS + N_NODES / 128, 256, FL_SMEM>>>(
        d_weh + weoff[0], d_wel + weoff[0], att[0], d_xl, d_xr, d_elog, d_eself, 512);
    softmax_stats<<<(N_NODES * 32 + 255) / 256, 256>>>();
    aggregate<2, true><<<N_NODES, 256>>>(bc[0], nullptr, d_Ah, d_Al, 512);

    // layer 2
    {
        dim3 g(2 * 1024 / 128, N_NODES / 128);
        gemm4w<<<g, 128, G4_SMEM>>>(d_Ah, d_Al, d_Wh + woff[2], d_Wlo + woff[2],
                                    d_Wh + woff[3], d_Wlo + woff[3],
                                    bl[1], br[1], d_xl, d_xr, N_NODES, 1024, 512);
    }
    fused_logit<<<FL_EDGE_BLOCKS + N_NODES / 128, 256, FL_SMEM>>>(
        d_weh + weoff[1], d_wel + weoff[1], att[1], d_xl, d_xr, d_elog, d_eself, 1024);
    softmax_stats<<<(N_NODES * 32 + 255) / 256, 256>>>();
    aggregate<4, true><<<N_NODES, 256>>>(bc[1], nullptr, d_Ah, d_Al, 1024);

    // layer 3
    {
        dim3 g(2 * 256 / 128, N_NODES / 128);
        gemm4w<<<g, 128, G4_SMEM>>>(d_Ah, d_Al, d_Wh + woff[4], d_Wlo + woff[4],
                                    d_Wh + woff[5], d_Wlo + woff[5],
                                    bl[2], br[2], d_xl, d_xr, N_NODES, 256, 1024);
    }
    fused_logit<<<FL_EDGE_BLOCKS + N_NODES / 128, 256, FL_SMEM>>>(
        d_weh + weoff[2], d_wel + weoff[2], att[2], d_xl, d_xr, d_elog, d_eself, 256);
    softmax_stats<<<(N_NODES * 32 + 255) / 256, 256>>>();
    aggregate<1, false><<<N_NODES, 256>>>(bc[2], d_hA, nullptr, nullptr, 256);

    // pool + MLP head
    pool_graph<<<NGRAPH, 256>>>(d_hA, batch);
    fc1_kernel<<<(NGRAPH * 64 + 255) / 256, 256>>>(fc1w, fc1b);
    head_kernel<<<1, 256>>>(bng, bnb, fc2w, fc2b, out);
}

// round 17
// speedup vs baseline: 1.1097x; 1.1097x over previous
#include <cuda_runtime.h>
#include <cuda_fp16.h>
#include <cuda_pipeline.h>
#include <mma.h>
#include <cstdint>

using namespace nvcuda;

#define N_NODES 16384
#define N_EDGES 131072
#define ED      32
#define NGRAPH  128
#define MAXF    1024
#define NEG_SLOPE 0.2f

// ---------------- scratch (static device memory; no allocs) ----------------
__device__ float g_hA[(size_t)N_NODES * 256];      // layer-3 output (fp32, for pool)
__device__ float g_xl[(size_t)N_NODES * MAXF];
__device__ float g_xr[(size_t)N_NODES * MAXF];
__device__ __half g_Ah[(size_t)N_NODES * MAXF];    // split activations hi
__device__ __half g_Al[(size_t)N_NODES * MAXF];    // lo
#define WOFF_L1 0
#define WOFF_R1 131072
#define WOFF_L2 262144
#define WOFF_R2 786432
#define WOFF_L3 1310720
#define WOFF_R3 1572864
#define WTOTAL  1835008
__device__ __half g_Wh[WTOTAL];
__device__ __half g_Wlo[WTOTAL];
#define WEOFF_1 0
#define WEOFF_2 16384
#define WEOFF_3 49152
#define WETOTAL 57344
__device__ __half g_weh[WETOTAL];
__device__ __half g_wel[WETOTAL];
__device__ __half g_eah[(size_t)N_EDGES * ED];
__device__ __half g_eal[(size_t)N_EDGES * ED];
__device__ __half g_lah[N_NODES * ED];
__device__ __half g_lal[N_NODES * ED];
__device__ int   g_deg[N_NODES];
__device__ int   g_off[N_NODES + 1];
__device__ int   g_cur[N_NODES];
__device__ int   g_ssrc[N_EDGES];
__device__ int   g_sdst[N_EDGES];
__device__ int   g_seid[N_EDGES];
__device__ float g_elog[N_EDGES];     // logits, then normalized alphas (in-place)
__device__ float g_eself[N_NODES];    // self logit, then alpha_self
__device__ float g_pool[NGRAPH * 256];
__device__ float g_z[NGRAPH * 64];

// ---------------- utility kernels ----------------
__global__ void zero_deg_cur() {
    int i = blockIdx.x * blockDim.x + threadIdx.x;
    if (i < N_NODES) { g_deg[i] = 0; g_cur[i] = 0; }
}

__global__ void count_deg(const int* __restrict__ dst) {
    int i = blockIdx.x * blockDim.x + threadIdx.x;
    if (i < N_EDGES) atomicAdd(&g_deg[dst[i]], 1);
}

__global__ void scan_deg() {
    int tid = threadIdx.x, lane = tid & 31, warp = tid >> 5;
    int base = tid * 16;
    int loc[16];
    int s = 0;
#pragma unroll
    for (int k = 0; k < 16; k++) { loc[k] = s; s += g_deg[base + k]; }
    int mysum = s;
#pragma unroll
    for (int o = 1; o < 32; o <<= 1) {
        int v = __shfl_up_sync(0xffffffffu, s, o);
        if (lane >= o) s += v;
    }
    __shared__ int wsum[32];
    if (lane == 31) wsum[warp] = s;
    __syncthreads();
    if (warp == 0) {
        int v = wsum[lane];
#pragma unroll
        for (int o = 1; o < 32; o <<= 1) {
            int u = __shfl_up_sync(0xffffffffu, v, o);
            if (lane >= o) v += u;
        }
        wsum[lane] = v;
    }
    __syncthreads();
    int excl = s - mysum + (warp ? wsum[warp - 1] : 0);
#pragma unroll
    for (int k = 0; k < 16; k++) g_off[base + k] = excl + loc[k];
    if (tid == 1023) g_off[N_NODES] = excl + mysum;
}

__global__ void scatter_edges(const int* __restrict__ src, const int* __restrict__ dst) {
    int i = blockIdx.x * blockDim.x + threadIdx.x;
    if (i >= N_EDGES) return;
    int d = dst[i];
    int p = g_off[d] + atomicAdd(&g_cur[d], 1);
    g_ssrc[p] = src[i];
    g_sdst[p] = d;
    g_seid[p] = i;
}

__global__ void ea_presplit(const float* __restrict__ ea) {
    int idx = blockIdx.x * blockDim.x + threadIdx.x;
    if (idx >= N_EDGES * 8) return;
    int p = idx >> 3, q = idx & 7;
    int row = g_seid[p];
    float4 v = *reinterpret_cast<const float4*>(&ea[(size_t)row * ED + q * 4]);
    float vv[4] = {v.x, v.y, v.z, v.w};
    __half h[4], l[4];
#pragma unroll
    for (int i = 0; i < 4; i++) {
        h[i] = __float2half_rn(vv[i]);
        l[i] = __float2half_rn(vv[i] - __half2float(h[i]));
    }
    *reinterpret_cast<uint2*>(&g_eah[(size_t)p * ED + q * 4]) = *reinterpret_cast<uint2*>(h);
    *reinterpret_cast<uint2*>(&g_eal[(size_t)p * ED + q * 4]) = *reinterpret_cast<uint2*>(l);
}

__global__ void loop_attr_csr(const float* __restrict__ ea) {
    int w = (blockIdx.x * blockDim.x + threadIdx.x) >> 5;
    int lane = threadIdx.x & 31;
    if (w >= N_NODES) return;
    int off = g_off[w], deg = g_off[w + 1] - off;
    float a = 0.0f;
    for (int j = 0; j < deg; j++)
        a += ea[(size_t)g_seid[off + j] * ED + lane];
    a /= fmaxf((float)deg, 1.0f);
    __half h = __float2half_rn(a);
    g_lah[w * ED + lane] = h;
    g_lal[w * ED + lane] = __float2half_rn(a - __half2float(h));
}

// ---------------- fp32 -> (hi,lo) fp16 split ----------------
__global__ void split_kernel(const float* __restrict__ in,
                             __half* __restrict__ hi, __half* __restrict__ lo, int n) {
    int base = (blockIdx.x * blockDim.x + threadIdx.x) * 4;
    if (base >= n) return;
    float4 v = *reinterpret_cast<const float4*>(in + base);
    float vv[4] = {v.x, v.y, v.z, v.w};
    __half h[4], l[4];
#pragma unroll
    for (int i = 0; i < 4; i++) {
        h[i] = __float2half_rn(vv[i]);
        l[i] = __float2half_rn(vv[i] - __half2float(h[i]));
    }
    *reinterpret_cast<uint2*>(hi + base) = *reinterpret_cast<uint2*>(h);
    *reinterpret_cast<uint2*>(lo + base) = *reinterpret_cast<uint2*>(l);
}

// ------- pre-split fp16x2 GEMM, 4 warps x 64x64 tiles, 2-stage cp.async -------
#define G4_LDA 40
#define G4_LDB 136
#define G4_AOFF_L 5120
#define G4_BOFF   10240
#define G4_BOFF_L 14592
#define G4_STAGE  18944
#define G4_SMEM   (2 * G4_STAGE * 2)      // 75776 B -> 2 CTAs/SM

__global__ __launch_bounds__(128, 2) void gemm4w(
    const __half* __restrict__ Ah, const __half* __restrict__ Al,
    const __half* __restrict__ B0h, const __half* __restrict__ B0l,
    const __half* __restrict__ B1h, const __half* __restrict__ B1l,
    const float* __restrict__ bias0, const float* __restrict__ bias1,
    float* __restrict__ C0, float* __restrict__ C1,
    int M, int Nw, int K) {
    extern __shared__ char gsm[];
    __half* sm = reinterpret_cast<__half*>(gsm);

    int tid = threadIdx.x;
    int warp = tid >> 5, lane = tid & 31;
    int wr = warp >> 1, wc = warp & 1;
    int nbx = Nw >> 7;
    int bx = blockIdx.x;
    const __half *Bh, *Bl;
    const float* bias;
    float* C;
    int col0;
    if (bx < nbx) { Bh = B0h; Bl = B0l; bias = bias0; C = C0; col0 = bx << 7; }
    else          { Bh = B1h; Bl = B1l; bias = bias1; C = C1; col0 = (bx - nbx) << 7; }
    int row0 = blockIdx.y << 7;

    wmma::fragment<wmma::accumulator, 16, 16, 16, float> cf[4][4];
#pragma unroll
    for (int r = 0; r < 4; r++)
#pragma unroll
        for (int c = 0; c < 4; c++) wmma::fill_fragment(cf[r][c], 0.0f);

    auto copy_stage = [&](int t) {
        int k0 = t * 32;
        __half* sb = sm + (t & 1) * G4_STAGE;
#pragma unroll
        for (int q = 0; q < 4; q++) {
            int idx = tid + q * 128;
            int r = idx >> 2, c = idx & 3;
            __pipeline_memcpy_async(&sb[r * G4_LDA + c * 8],
                                    &Ah[(size_t)(row0 + r) * K + k0 + c * 8], 16);
            __pipeline_memcpy_async(&sb[G4_AOFF_L + r * G4_LDA + c * 8],
                                    &Al[(size_t)(row0 + r) * K + k0 + c * 8], 16);
            int rb = idx >> 4, cb = idx & 15;
            __pipeline_memcpy_async(&sb[G4_BOFF + rb * G4_LDB + cb * 8],
                                    &Bh[(size_t)(k0 + rb) * Nw + col0 + cb * 8], 16);
            __pipeline_memcpy_async(&sb[G4_BOFF_L + rb * G4_LDB + cb * 8],
                                    &Bl[(size_t)(k0 + rb) * Nw + col0 + cb * 8], 16);
        }
    };
    auto compute = [&](int slot) {
        const __half* sb = sm + slot * G4_STAGE;
#pragma unroll
        for (int ks = 0; ks < 2; ks++) {
            wmma::fragment<wmma::matrix_a, 16, 16, 16, __half, wmma::row_major> ah[4], al[4];
            wmma::fragment<wmma::matrix_b, 16, 16, 16, __half, wmma::row_major> bh[4], bl[4];
#pragma unroll
            for (int r = 0; r < 4; r++) {
                int aoff = (wr * 64 + r * 16) * G4_LDA + ks * 16;
                wmma::load_matrix_sync(ah[r], &sb[aoff], G4_LDA);
                wmma::load_matrix_sync(al[r], &sb[G4_AOFF_L + aoff], G4_LDA);
            }
#pragma unroll
            for (int c = 0; c < 4; c++) {
                int boff = (ks * 16) * G4_LDB + wc * 64 + c * 16;
                wmma::load_matrix_sync(bh[c], &sb[G4_BOFF + boff], G4_LDB);
                wmma::load_matrix_sync(bl[c], &sb[G4_BOFF_L + boff], G4_LDB);
            }
#pragma unroll
            for (int r = 0; r < 4; r++)
#pragma unroll
                for (int c = 0; c < 4; c++) {
                    wmma::mma_sync(cf[r][c], ah[r], bl[c], cf[r][c]);
                    wmma::mma_sync(cf[r][c], al[r], bh[c], cf[r][c]);
                    wmma::mma_sync(cf[r][c], ah[r], bh[c], cf[r][c]);
                }
        }
    };

    int nk = K >> 5;
    copy_stage(0);
    __pipeline_commit();
    for (int t = 0; t < nk; t++) {
        __pipeline_wait_prior(0);
        __syncthreads();
        if (t + 1 < nk) {
            copy_stage(t + 1);
            __pipeline_commit();
        }
        compute(t & 1);
    }
    __syncthreads();

    float* Ep = reinterpret_cast<float*>(gsm) + warp * 16 * 20;
    int erow = lane >> 1;
    int ecol = (lane & 1) * 8;
#pragma unroll
    for (int r = 0; r < 4; r++) {
#pragma unroll
        for (int c = 0; c < 4; c++) {
            wmma::store_matrix_sync(Ep, cf[r][c], 20, wmma::mem_row_major);
            __syncwarp();
            int rr = row0 + wr * 64 + r * 16 + erow;
            int cc = col0 + wc * 64 + c * 16 + ecol;
            float4 v0 = *reinterpret_cast<float4*>(&Ep[erow * 20 + ecol]);
            float4 v1 = *reinterpret_cast<float4*>(&Ep[erow * 20 + ecol + 4]);
            float4 b0 = *reinterpret_cast<const float4*>(&bias[cc]);
            float4 b1 = *reinterpret_cast<const float4*>(&bias[cc + 4]);
            v0.x += b0.x; v0.y += b0.y; v0.z += b0.z; v0.w += b0.w;
            v1.x += b1.x; v1.y += b1.y; v1.z += b1.z; v1.w += b1.w;
            *reinterpret_cast<float4*>(&C[(size_t)rr * Nw + cc])     = v0;
            *reinterpret_cast<float4*>(&C[(size_t)rr * Nw + cc + 4]) = v1;
            __syncwarp();
        }
    }
}

// ------- fused attention logits (edges + self-loops in ONE launch) -------
#define FL_LDE 40
#define FL_LDW 136
#define FL_LDZ 132
#define FL_SMEM (2*128*FL_LDE*2 + 2*32*FL_LDW*2 + 128*FL_LDZ*4 + 2*128*4)
#define FL_EDGE_BLOCKS (N_EDGES / 128)

__global__ __launch_bounds__(256) void fused_logit(
    const __half* __restrict__ weh, const __half* __restrict__ wel,
    const float* __restrict__ att,
    const float* __restrict__ xl, const float* __restrict__ xr,
    float* __restrict__ elog, float* __restrict__ eself, int F) {
    extern __shared__ char sm_raw[];
    __half* ea_h = reinterpret_cast<__half*>(sm_raw);
    __half* ea_l = ea_h + 128 * FL_LDE;
    __half* w_h  = ea_l + 128 * FL_LDE;
    __half* w_l  = w_h + 32 * FL_LDW;
    float*  sz   = reinterpret_cast<float*>(w_l + 32 * FL_LDW);
    int* s_src = reinterpret_cast<int*>(sz + 128 * FL_LDZ);
    int* s_dst = s_src + 128;

    int tid = threadIdx.x, warp = tid >> 5, lane = tid & 31;
    int wr = warp >> 2, wc = warp & 3;
    int mode = (blockIdx.x >= FL_EDGE_BLOCKS) ? 1 : 0;
    int tile0 = (mode == 0) ? blockIdx.x * 128 : (blockIdx.x - FL_EDGE_BLOCKS) * 128;
    const __half* eah = (mode == 0) ? g_eah : g_lah;
    const __half* eal = (mode == 0) ? g_eal : g_lal;
    float* out_log = (mode == 0) ? elog : eself;

    if (tid < 128) {
        if (mode == 0) { s_src[tid] = g_ssrc[tile0 + tid]; s_dst[tid] = g_sdst[tile0 + tid]; }
        else           { s_src[tid] = tile0 + tid;         s_dst[tid] = tile0 + tid; }
    }
    {
        size_t base = (size_t)tile0 * ED;
#pragma unroll
        for (int q = 0; q < 2; q++) {
            int ch = tid + q * 256;
            int r = ch >> 2, c8 = ch & 3;
            *reinterpret_cast<uint4*>(&ea_h[r * FL_LDE + c8 * 8]) =
                __ldg(reinterpret_cast<const uint4*>(&eah[base + ch * 8]));
            *reinterpret_cast<uint4*>(&ea_l[r * FL_LDE + c8 * 8]) =
                __ldg(reinterpret_cast<const uint4*>(&eal[base + ch * 8]));
        }
    }
    __syncthreads();

    float acc[16];
#pragma unroll
    for (int e = 0; e < 16; e++) acc[e] = 0.0f;
    int we0 = warp * 16;

    for (int f0 = 0; f0 < F; f0 += 128) {
#pragma unroll
        for (int q = 0; q < 2; q++) {
            int ch = tid + q * 256;
            int r = ch >> 4, c8 = ch & 15;
            *reinterpret_cast<uint4*>(&w_h[r * FL_LDW + c8 * 8]) =
                __ldg(reinterpret_cast<const uint4*>(&weh[(size_t)r * F + f0 + c8 * 8]));
            *reinterpret_cast<uint4*>(&w_l[r * FL_LDW + c8 * 8]) =
                __ldg(reinterpret_cast<const uint4*>(&wel[(size_t)r * F + f0 + c8 * 8]));
        }
        __syncthreads();

        wmma::fragment<wmma::accumulator, 16, 16, 16, float> cf[4][2];
#pragma unroll
        for (int r = 0; r < 4; r++)
#pragma unroll
            for (int c = 0; c < 2; c++) wmma::fill_fragment(cf[r][c], 0.0f);
#pragma unroll
        for (int ks = 0; ks < 2; ks++) {
            wmma::fragment<wmma::matrix_a, 16, 16, 16, __half, wmma::row_major> ah[4], al[4];
            wmma::fragment<wmma::matrix_b, 16, 16, 16, __half, wmma::row_major> bh[2], bl[2];
#pragma unroll
            for (int r = 0; r < 4; r++) {
                int aoff = (wr * 64 + r * 16) * FL_LDE + ks * 16;
                wmma::load_matrix_sync(ah[r], &ea_h[aoff], FL_LDE);
                wmma::load_matrix_sync(al[r], &ea_l[aoff], FL_LDE);
            }
#pragma unroll
            for (int c = 0; c < 2; c++) {
                int boff = (ks * 16) * FL_LDW + wc * 32 + c * 16;
                wmma::load_matrix_sync(bh[c], &w_h[boff], FL_LDW);
                wmma::load_matrix_sync(bl[c], &w_l[boff], FL_LDW);
            }
#pragma unroll
            for (int r = 0; r < 4; r++)
#pragma unroll
                for (int c = 0; c < 2; c++) {
                    wmma::mma_sync(cf[r][c], ah[r], bl[c], cf[r][c]);
                    wmma::mma_sync(cf[r][c], al[r], bh[c], cf[r][c]);
                    wmma::mma_sync(cf[r][c], ah[r], bh[c], cf[r][c]);
                }
        }
#pragma unroll
        for (int r = 0; r < 4; r++)
#pragma unroll
            for (int c = 0; c < 2; c++)
                wmma::store_matrix_sync(&sz[(wr * 64 + r * 16) * FL_LDZ + wc * 32 + c * 16],
                                        cf[r][c], FL_LDZ, wmma::mem_row_major);
        __syncthreads();

        float4 av = *reinterpret_cast<const float4*>(&att[f0 + lane * 4]);
#pragma unroll
        for (int e = 0; e < 16; e++) {
            int idx = we0 + e;
            float4 vl = __ldg(reinterpret_cast<const float4*>(xl + (size_t)s_src[idx] * F + f0 + lane * 4));
            float4 vr = __ldg(reinterpret_cast<const float4*>(xr + (size_t)s_dst[idx] * F + f0 + lane * 4));
            float4 vz = *reinterpret_cast<const float4*>(&sz[idx * FL_LDZ + lane * 4]);
            float v0 = vl.x + vr.x + vz.x; v0 = (v0 > 0.0f) ? v0 : NEG_SLOPE * v0;
            float v1 = vl.y + vr.y + vz.y; v1 = (v1 > 0.0f) ? v1 : NEG_SLOPE * v1;
            float v2 = vl.z + vr.z + vz.z; v2 = (v2 > 0.0f) ? v2 : NEG_SLOPE * v2;
            float v3 = vl.w + vr.w + vz.w; v3 = (v3 > 0.0f) ? v3 : NEG_SLOPE * v3;
            acc[e] += v0 * av.x + v1 * av.y + v2 * av.z + v3 * av.w;
        }
        __syncthreads();
    }
#pragma unroll
    for (int e = 0; e < 16; e++) {
        float a = acc[e];
#pragma unroll
        for (int o = 16; o; o >>= 1) a += __shfl_xor_sync(0xffffffffu, a, o);
        if (lane == 0) out_log[tile0 + we0 + e] = a;
    }
}

// ------- per-node softmax stats: logits -> normalized alphas (in-place) -------
__global__ void softmax_stats() {
    int n = (blockIdx.x * blockDim.x + threadIdx.x) >> 5;
    int lane = threadIdx.x & 31;
    if (n >= N_NODES) return;
    int off = g_off[n], deg = g_off[n + 1] - off;
    float es = g_eself[n];
    float m = es;
    for (int j = lane; j < deg; j += 32) m = fmaxf(m, g_elog[off + j]);
#pragma unroll
    for (int o = 16; o; o >>= 1) m = fmaxf(m, __shfl_xor_sync(0xffffffffu, m, o));
    float s = 0.0f;
    for (int j = lane; j < deg; j += 32) s += __expf(g_elog[off + j] - m);
#pragma unroll
    for (int o = 16; o; o >>= 1) s += __shfl_xor_sync(0xffffffffu, s, o);
    float esx = __expf(es - m);
    float inv = 1.0f / (s + esx);
    for (int j = lane; j < deg; j += 32)
        g_elog[off + j] = __expf(g_elog[off + j] - m) * inv;
    if (lane == 0) g_eself[n] = esx * inv;
}

// ------- aggregate: weighted gather using precomputed alphas (+bias+relu) -------
template <int NR, bool SPLIT>
__global__ __launch_bounds__(256) void aggregate(const float* __restrict__ bc,
                                                 float* __restrict__ outf,
                                                 __half* __restrict__ outh,
                                                 __half* __restrict__ outl, int F) {
    int n = blockIdx.x;
    int tid = threadIdx.x;
    int off = g_off[n];
    int deg = g_off[n + 1] - off;
    __shared__ float s_alpha[256];
    __shared__ int s_src[256];

    int f0 = tid * NR;
    float acc[NR];
    const float* xln = &g_xl[(size_t)n * F];
    float aself = g_eself[n];
#pragma unroll
    for (int i = 0; i < NR; i++) acc[i] = aself * xln[f0 + i];

    for (int c0 = 0; c0 < deg; c0 += 256) {
        int cnt = min(256, deg - c0);
        if (tid < cnt) {
            s_alpha[tid] = g_elog[off + c0 + tid];
            s_src[tid] = g_ssrc[off + c0 + tid];
        }
        __syncthreads();
        for (int j = 0; j < cnt; j++) {
            const float* xs = &g_xl[(size_t)s_src[j] * F];
            float a = s_alpha[j];
            if (NR == 4) {
                float4 v = __ldg(reinterpret_cast<const float4*>(xs + f0));
                acc[0] += a * v.x; acc[1] += a * v.y;
                acc[2] += a * v.z; acc[3] += a * v.w;
            } else if (NR == 2) {
                float2 v = __ldg(reinterpret_cast<const float2*>(xs + f0));
                acc[0] += a * v.x; acc[1] += a * v.y;
            } else {
                acc[0] += a * __ldg(xs + f0);
            }
        }
        __syncthreads();
    }
    if (SPLIT) {
        __half h[NR], l[NR];
#pragma unroll
        for (int i = 0; i < NR; i++) {
            float v = fmaxf(acc[i] + bc[f0 + i], 0.0f);
            h[i] = __float2half_rn(v);
            l[i] = __float2half_rn(v - __half2float(h[i]));
        }
        size_t o = (size_t)n * F + f0;
        if (NR == 4) {
            *reinterpret_cast<uint2*>(&outh[o]) = *reinterpret_cast<uint2*>(h);
            *reinterpret_cast<uint2*>(&outl[o]) = *reinterpret_cast<uint2*>(l);
        } else {
            *reinterpret_cast<uint32_t*>(&outh[o]) = *reinterpret_cast<uint32_t*>(h);
            *reinterpret_cast<uint32_t*>(&outl[o]) = *reinterpret_cast<uint32_t*>(l);
        }
    } else {
#pragma unroll
        for (int i = 0; i < NR; i++)
            outf[(size_t)n * F + f0 + i] = fmaxf(acc[i] + bc[f0 + i], 0.0f);
    }
}

// ---------------- pooling ----------------
__global__ __launch_bounds__(256) void pool_graph(const float* __restrict__ h,
                                                  const int* __restrict__ batch) {
    int g = blockIdx.x;
    int tid = threadIdx.x;
    __shared__ int s_lo, s_hi;
    if (tid == 0) {
        int lo = 0, hi = N_NODES;
        while (lo < hi) { int mid = (lo + hi) >> 1; if (batch[mid] < g) lo = mid + 1; else hi = mid; }
        s_lo = lo;
        lo = 0; hi = N_NODES;
        while (lo < hi) { int mid = (lo + hi) >> 1; if (batch[mid] < g + 1) lo = mid + 1; else hi = mid; }
        s_hi = lo;
    }
    __syncthreads();
    int lo = s_lo, hi = s_hi;
    float acc = 0.0f;
    for (int n = lo; n < hi; n++) acc += h[(size_t)n * 256 + tid];
    g_pool[g * 256 + tid] = acc / fmaxf((float)(hi - lo), 1.0f);
}

// ---------------- MLP head ----------------
__global__ void fc1_kernel(const float* __restrict__ fc1w, const float* __restrict__ fc1b) {
    int i = blockIdx.x * blockDim.x + threadIdx.x;
    if (i >= NGRAPH * 64) return;
    int g = i >> 6, o = i & 63;
    float s = 0.0f;
    for (int k = 0; k < 256; k++) s += g_pool[g * 256 + k] * fc1w[k * 64 + o];
    g_z[i] = s + fc1b[o];
}

__global__ __launch_bounds__(256) void head_kernel(
    const float* __restrict__ bng, const float* __restrict__ bnb,
    const float* __restrict__ fc2w, const float* __restrict__ fc2b,
    float* __restrict__ out) {
    __shared__ float z[NGRAPH * 64];
    __shared__ float mu[64], iv[64];
    int tid = threadIdx.x;
    for (int i = tid; i < NGRAPH * 64; i += 256) z[i] = g_z[i];
    __syncthreads();
    if (tid < 64) {
        float s = 0.0f, s2 = 0.0f;
        for (int g = 0; g < NGRAPH; g++) {
            float v = z[g * 64 + tid];
            s += v; s2 += v * v;
        }
        float mean = s / (float)NGRAPH;
        float var = s2 / (float)NGRAPH - mean * mean;
        mu[tid] = mean;
        iv[tid] = rsqrtf(var + 1e-5f);
    }
    __syncthreads();
    for (int i = tid; i < NGRAPH * 64; i += 256) {
        int o = i & 63;
        float v = (z[i] - mu[o]) * iv[o] * bng[o] + bnb[o];
        z[i] = fmaxf(v, 0.0f);
    }
    __syncthreads();
    if (tid < NGRAPH) {
        float s = 0.0f;
        for (int o = 0; o < 64; o++) s += z[tid * 64 + o] * fc2w[o];
        out[tid] = s + fc2b[0];
    }
}

extern "C" void kernel_launch(void* const* d_in, const int* in_sizes, int n_in,
                              void* d_out, int out_size) {
    const float* x         = (const float*)d_in[0];
    const int*   ei        = (const int*)d_in[1];
    const float* edge_attr = (const float*)d_in[2];
    const int*   batch     = (const int*)d_in[3];

    const float* Wl[3], *bl[3], *Wr[3], *br[3], *We[3], *att[3], *bc[3];
    for (int l = 0; l < 3; l++) {
        int b = 4 + l * 7;
        Wl[l]  = (const float*)d_in[b + 0];
        bl[l]  = (const float*)d_in[b + 1];
        Wr[l]  = (const float*)d_in[b + 2];
        br[l]  = (const float*)d_in[b + 3];
        We[l]  = (const float*)d_in[b + 4];
        att[l] = (const float*)d_in[b + 5];
        bc[l]  = (const float*)d_in[b + 6];
    }
    const float* fc1w = (const float*)d_in[25];
    const float* fc1b = (const float*)d_in[26];
    const float* bng  = (const float*)d_in[27];
    const float* bnb  = (const float*)d_in[28];
    const float* fc2w = (const float*)d_in[29];
    const float* fc2b = (const float*)d_in[30];
    float* out = (float*)d_out;

    const int* src = ei;
    const int* dst = ei + N_EDGES;

    static cudaStream_t s2 = nullptr;
    static cudaEvent_t ev_fork = nullptr, ev_join = nullptr;
    static bool attr_set = false;
    if (!attr_set) {
        cudaFuncSetAttribute(fused_logit, cudaFuncAttributeMaxDynamicSharedMemorySize, FL_SMEM);
        cudaFuncSetAttribute(gemm4w, cudaFuncAttributeMaxDynamicSharedMemorySize, G4_SMEM);
        cudaStreamCreateWithFlags(&s2, cudaStreamNonBlocking);
        cudaEventCreateWithFlags(&ev_fork, cudaEventDisableTiming);
        cudaEventCreateWithFlags(&ev_join, cudaEventDisableTiming);
        attr_set = true;
    }

    float *d_hA, *d_xl, *d_xr, *d_elog, *d_eself;
    __half *d_Ah, *d_Al, *d_Wh, *d_Wlo, *d_weh, *d_wel;
    cudaGetSymbolAddress((void**)&d_hA, g_hA);
    cudaGetSymbolAddress((void**)&d_xl, g_xl);
    cudaGetSymbolAddress((void**)&d_xr, g_xr);
    cudaGetSymbolAddress((void**)&d_elog, g_elog);
    cudaGetSymbolAddress((void**)&d_eself, g_eself);
    cudaGetSymbolAddress((void**)&d_Ah, g_Ah);
    cudaGetSymbolAddress((void**)&d_Al, g_Al);
    cudaGetSymbolAddress((void**)&d_Wh, g_Wh);
    cudaGetSymbolAddress((void**)&d_Wlo, g_Wlo);
    cudaGetSymbolAddress((void**)&d_weh, g_weh);
    cudaGetSymbolAddress((void**)&d_wel, g_wel);

    const int woff[6]  = {WOFF_L1, WOFF_R1, WOFF_L2, WOFF_R2, WOFF_L3, WOFF_R3};
    const int wsz[3]   = {256 * 512, 512 * 1024, 1024 * 256};
    const int weoff[3] = {WEOFF_1, WEOFF_2, WEOFF_3};
    const int Fout[3]  = {512, 1024, 256};

    // ---- fork: preprocessing + remaining splits on side stream s2 ----
    cudaEventRecord(ev_fork, 0);
    cudaStreamWaitEvent(s2, ev_fork, 0);

    zero_deg_cur<<<(N_NODES + 255) / 256, 256, 0, s2>>>();
    count_deg<<<(N_EDGES + 255) / 256, 256, 0, s2>>>(dst);
    scan_deg<<<1, 1024, 0, s2>>>();
    scatter_edges<<<(N_EDGES + 255) / 256, 256, 0, s2>>>(src, dst);
    ea_presplit<<<(N_EDGES * 8 + 255) / 256, 256, 0, s2>>>(edge_attr);
    loop_attr_csr<<<(N_NODES * 32 + 255) / 256, 256, 0, s2>>>(edge_attr);
    split_kernel<<<(wsz[1] / 4 + 255) / 256, 256, 0, s2>>>(Wl[1], d_Wh + woff[2], d_Wlo + woff[2], wsz[1]);
    split_kernel<<<(wsz[1] / 4 + 255) / 256, 256, 0, s2>>>(Wr[1], d_Wh + woff[3], d_Wlo + woff[3], wsz[1]);
    split_kernel<<<(wsz[2] / 4 + 255) / 256, 256, 0, s2>>>(Wl[2], d_Wh + woff[4], d_Wlo + woff[4], wsz[2]);
    split_kernel<<<(wsz[2] / 4 + 255) / 256, 256, 0, s2>>>(Wr[2], d_Wh + woff[5], d_Wlo + woff[5], wsz[2]);
    for (int l = 0; l < 3; l++) {
        int n = ED * Fout[l];
        split_kernel<<<(n / 4 + 255) / 256, 256, 0, s2>>>(We[l], d_weh + weoff[l], d_wel + weoff[l], n);
    }
    cudaEventRecord(ev_join, s2);

    // main stream: x split + layer-1 weight splits + layer-1 GEMM (overlaps s2)
    split_kernel<<<(N_NODES * 256 / 4) / 256, 256>>>(x, d_Ah, d_Al, N_NODES * 256);
    split_kernel<<<(wsz[0] / 4 + 255) / 256, 256>>>(Wl[0], d_Wh + woff[0], d_Wlo + woff[0], wsz[0]);
    split_kernel<<<(wsz[0] / 4 + 255) / 256, 256>>>(Wr[0], d_Wh + woff[1], d_Wlo + woff[1], wsz[0]);
    {
        dim3 g(2 * 512 / 128, N_NODES / 128);
        gemm4w<<<g, 128, G4_SMEM>>>(d_Ah, d_Al, d_Wh + woff[0], d_Wlo + woff[0],
                                    d_Wh + woff[1], d_Wlo + woff[1],
                                    bl[0], br[0], d_xl, d_xr, N_NODES, 512, 256);
    }
    cudaStreamWaitEvent(0, ev_join, 0);

    // layer 1
    fused_logit<<<FL_EDGE_BLOCKS + N_NODES / 128, 256, FL_SMEM>>>(
        d_weh + weoff[0], d_wel + weoff[0], att[0], d_xl, d_xr, d_elog, d_eself, 512);
    softmax_stats<<<(N_NODES * 32 + 255) / 256, 256>>>();
    aggregate<2, true><<<N_NODES, 256>>>(bc[0], nullptr, d_Ah, d_Al, 512);

    // layer 2
    {
        dim3 g(2 * 1024 / 128, N_NODES / 128);
        gemm4w<<<g, 128, G4_SMEM>>>(d_Ah, d_Al, d_Wh + woff[2], d_Wlo + woff[2],
                                    d_Wh + woff[3], d_Wlo + woff[3],
                                    bl[1], br[1], d_xl, d_xr, N_NODES, 1024, 512);
    }
    fused_logit<<<FL_EDGE_BLOCKS + N_NODES / 128, 256, FL_SMEM>>>(
        d_weh + weoff[1], d_wel + weoff[1], att[1], d_xl, d_xr, d_elog, d_eself, 1024);
    softmax_stats<<<(N_NODES * 32 + 255) / 256, 256>>>();
    aggregate<4, true><<<N_NODES, 256>>>(bc[1], nullptr, d_Ah, d_Al, 1024);

    // layer 3
    {
        dim3 g(2 * 256 / 128, N_NODES / 128);
        gemm4w<<<g, 128, G4_SMEM>>>(d_Ah, d_Al, d_Wh + woff[4], d_Wlo + woff[4],
                                    d_Wh + woff[5], d_Wlo + woff[5],
                                    bl[2], br[2], d_xl, d_xr, N_NODES, 256, 1024);
    }
    fused_logit<<<FL_EDGE_BLOCKS + N_NODES / 128, 256, FL_SMEM>>>(
        d_weh + weoff[2], d_wel + weoff[2], att[2], d_xl, d_xr, d_elog, d_eself, 256);
    softmax_stats<<<(N_NODES * 32 + 255) / 256, 256>>>();
    aggregate<1, false><<<N_NODES, 256>>>(bc[2], d_hA, nullptr, nullptr, 256);

    // pool + MLP head
    pool_graph<<<NGRAPH, 256>>>(d_hA, batch);
    fc1_kernel<<<(NGRAPH * 64 + 255) / 256, 256>>>(fc1w, fc1b);
    head_kernel<<<1, 256>>>(bng, bnb, fc2w, fc2b, out);
}